// round 11
// baseline (speedup 1.0000x reference)
#include <cuda_runtime.h>
#include <cuda_bf16.h>
#include <cstdint>

#define MARGIN 9.0f
#define NB  32
#define NEI 100000
#define ND  64
#define TPB 256
#define EPB 256       // 2 strips of 16 entities per warp
#define LDR 72        // padded q row length in bf16 (144 B): conflict-free ldmatrix/STS

// static smem: QH [32][72] bf16, QL [32][72] bf16, qn [32] f32  = 9344 B
#define SMEM_QH 0
#define SMEM_QL (32*LDR*2)
#define SMEM_QN (2*32*LDR*2)
__shared__ __align__(16) unsigned char smem_s[2*32*LDR*2 + 32*4];

__device__ __forceinline__ void ldsm_x4(uint32_t& r0, uint32_t& r1, uint32_t& r2, uint32_t& r3,
                                        uint32_t addr) {
    asm volatile("ldmatrix.sync.aligned.m8n8.x4.shared.b16 {%0,%1,%2,%3}, [%4];"
                 : "=r"(r0), "=r"(r1), "=r"(r2), "=r"(r3) : "r"(addr));
}
__device__ __forceinline__ void mma_bf16(float* c, const uint32_t* a, uint32_t b0, uint32_t b1) {
    asm volatile("mma.sync.aligned.m16n8k16.row.col.f32.bf16.bf16.f32 "
                 "{%0,%1,%2,%3}, {%4,%5,%6,%7}, {%8,%9}, {%0,%1,%2,%3};"
                 : "+f"(c[0]), "+f"(c[1]), "+f"(c[2]), "+f"(c[3])
                 : "r"(a[0]), "r"(a[1]), "r"(a[2]), "r"(a[3]), "r"(b0), "r"(b1));
}
// packed split of (v0,v1) into bf16x2 hi + bf16x2 lo (v0 in low half)
__device__ __forceinline__ void split_pair(float v0, float v1, uint32_t& hp, uint32_t& lp) {
    asm("cvt.rn.bf16x2.f32 %0, %1, %2;" : "=r"(hp) : "f"(v1), "f"(v0));
    uint32_t hf0u = hp << 16;
    uint32_t hf1u = hp & 0xFFFF0000u;
    float l0 = v0 - __uint_as_float(hf0u);
    float l1 = v1 - __uint_as_float(hf1u);
    asm("cvt.rn.bf16x2.f32 %0, %1, %2;" : "=r"(lp) : "f"(l1), "f"(l0));
}

__global__ void __launch_bounds__(TPB, 3) transe_kernel(
    const void* __restrict__ subp, const void* __restrict__ relp,
    const float* __restrict__ emb_e, const float* __restrict__ emb_rel,
    float* __restrict__ out)
{
    const int tid = threadIdx.x;
    const long long ebase = (long long)blockIdx.x * EPB;
    float* qn = (float*)(smem_s + SMEM_QN);

    const int wid = tid >> 5;
    const int ln  = tid & 31;
    const int nwarp = wid * 32;          // warp's 32-entity range (2 strips of 16)
    const int t = ln & 3;                // k-pair selector within fragment
    const int g = ln >> 2;               // n-row within n8 tile

    // ---- strip-0 B prefetch (kk=0,1) issued FIRST: hides DRAM latency under
    // the q gather chain + barrier. Rows clamped (last block): clamped columns
    // are never stored by the guarded epilogue.
    float2 buf[2][4];
    {
        long long n0 = ebase + nwarp + g;
        long long n1 = n0 + 8;
        if (n0 > NEI - 1) n0 = NEI - 1;
        if (n1 > NEI - 1) n1 = NEI - 1;
        const float* p0 = emb_e + n0 * ND + 2 * t;
        const float* p1 = emb_e + n1 * ND + 2 * t;
        #pragma unroll
        for (int kk = 0; kk < 2; kk++) {
            buf[kk][0] = *(const float2*)(p0 + kk*16);
            buf[kk][1] = *(const float2*)(p0 + kk*16 + 8);
            buf[kk][2] = *(const float2*)(p1 + kk*16);
            buf[kk][3] = *(const float2*)(p1 + kk*16 + 8);
        }
    }

    // ---- q fill: row = tid>>3, 8-dim chunk = tid&7; hi/lo bf16 to smem ----
    {
        // index dtype detection (jnp.int64 may silently be int32); 64B read safe.
        bool is64 = true;
        const long long* s64 = (const long long*)subp;
        #pragma unroll
        for (int i = 0; i < 8; i++) {
            long long v = s64[i];
            if (v < 0 || v >= NEI) is64 = false;
        }
        int row = tid >> 3;
        int ch  = tid & 7;                  // dims [ch*8, ch*8+8)
        long long s = is64 ? ((const long long*)subp)[row] : (long long)((const int*)subp)[row];
        long long r = is64 ? ((const long long*)relp)[row] : (long long)((const int*)relp)[row];
        float4 e0 = ((const float4*)emb_e)[s*16 + 2*ch];
        float4 e1 = ((const float4*)emb_e)[s*16 + 2*ch + 1];
        float4 r0v = ((const float4*)emb_rel)[r*16 + 2*ch];
        float4 r1v = ((const float4*)emb_rel)[r*16 + 2*ch + 1];
        float vv[8] = {e0.x+r0v.x, e0.y+r0v.y, e0.z+r0v.z, e0.w+r0v.w,
                       e1.x+r1v.x, e1.y+r1v.y, e1.z+r1v.z, e1.w+r1v.w};
        uint32_t hp[4], lp[4];
        float part = 0.f;
        #pragma unroll
        for (int j = 0; j < 4; j++) {
            split_pair(vv[2*j], vv[2*j+1], hp[j], lp[j]);
            part = fmaf(vv[2*j], vv[2*j], fmaf(vv[2*j+1], vv[2*j+1], part));
        }
        int off = (row*LDR + ch*8) * 2;
        *(uint4*)(smem_s + SMEM_QH + off) = make_uint4(hp[0],hp[1],hp[2],hp[3]);
        *(uint4*)(smem_s + SMEM_QL + off) = make_uint4(lp[0],lp[1],lp[2],lp[3]);
        part += __shfl_xor_sync(0xffffffffu, part, 1);
        part += __shfl_xor_sync(0xffffffffu, part, 2);
        part += __shfl_xor_sync(0xffffffffu, part, 4);
        if (ch == 0) qn[row] = part;
    }
    __syncthreads();

    // ---- A (Q) ldmatrix addresses (mapping validated in R8) ----
    uint32_t smem_u = (uint32_t)__cvta_generic_to_shared(smem_s);
    const int arow  = ln & 15;
    const int akoff = (ln >> 4) * 8;
    uint32_t aH = smem_u + SMEM_QH + (arow*LDR + akoff)*2;
    uint32_t aL = smem_u + SMEM_QL + (arow*LDR + akoff)*2;
    const int cb = 2 * t;

    // ---- strip loop: kept unroll 1 so frag/accum registers are reused ----
    #pragma unroll 1
    for (int s = 0; s < 2; s++) {
        const int nbase = nwarp + s * 16;
        long long n0 = ebase + nbase + g;
        long long n1 = n0 + 8;
        if (n0 > NEI - 1) n0 = NEI - 1;
        if (n1 > NEI - 1) n1 = NEI - 1;
        const float* pB0 = emb_e + n0 * ND + 2 * t;
        const float* pB1 = emb_e + n1 * ND + 2 * t;
        if (s > 0) {    // strip 0's kk=0,1 already in flight since kernel start
            #pragma unroll
            for (int kk = 0; kk < 2; kk++) {
                buf[kk][0] = *(const float2*)(pB0 + kk*16);
                buf[kk][1] = *(const float2*)(pB0 + kk*16 + 8);
                buf[kk][2] = *(const float2*)(pB1 + kk*16);
                buf[kk][3] = *(const float2*)(pB1 + kk*16 + 8);
            }
        }

        float c[2][2][4];
        #pragma unroll
        for (int mi = 0; mi < 2; mi++)
            #pragma unroll
            for (int nj = 0; nj < 2; nj++)
                #pragma unroll
                for (int j = 0; j < 4; j++) c[mi][nj][j] = 0.f;

        float en0 = 0.f, en1 = 0.f;

        #pragma unroll
        for (int kk = 0; kk < 4; kk++) {
            float2 f0 = buf[kk&1][0], f1 = buf[kk&1][1];
            float2 f2 = buf[kk&1][2], f3 = buf[kk&1][3];
            if (kk < 2) {
                int o = (kk + 2) * 16;
                buf[kk&1][0] = *(const float2*)(pB0 + o);
                buf[kk&1][1] = *(const float2*)(pB0 + o + 8);
                buf[kk&1][2] = *(const float2*)(pB1 + o);
                buf[kk&1][3] = *(const float2*)(pB1 + o + 8);
            }
            uint32_t bh0,bl0,bh1,bl1,bh2,bl2,bh3,bl3;
            split_pair(f0.x, f0.y, bh0, bl0);
            split_pair(f1.x, f1.y, bh1, bl1);
            split_pair(f2.x, f2.y, bh2, bl2);
            split_pair(f3.x, f3.y, bh3, bl3);
            en0 = fmaf(f0.x,f0.x, fmaf(f0.y,f0.y, fmaf(f1.x,f1.x, fmaf(f1.y,f1.y, en0))));
            en1 = fmaf(f2.x,f2.x, fmaf(f2.y,f2.y, fmaf(f3.x,f3.x, fmaf(f3.y,f3.y, en1))));
            const uint32_t ko = kk * 32;
            #pragma unroll
            for (int mi = 0; mi < 2; mi++) {
                uint32_t ah[4], al[4];
                ldsm_x4(ah[0],ah[1],ah[2],ah[3], aH + mi*16*LDR*2 + ko);
                ldsm_x4(al[0],al[1],al[2],al[3], aL + mi*16*LDR*2 + ko);
                // dot = Ah*Bh + Ah*Bl + Al*Bh   (lo*lo dropped, ~2^-16)
                mma_bf16(c[mi][0], ah, bh0, bh1);
                mma_bf16(c[mi][1], ah, bh2, bh3);
                mma_bf16(c[mi][0], ah, bl0, bl1);
                mma_bf16(c[mi][1], ah, bl2, bl3);
                mma_bf16(c[mi][0], al, bh0, bh1);
                mma_bf16(c[mi][1], al, bh2, bh3);
            }
        }

        // ---- entity norms: reduce over 4-lane k-group, redistribute to col owners ----
        en0 += __shfl_xor_sync(0xffffffffu, en0, 1);
        en0 += __shfl_xor_sync(0xffffffffu, en0, 2);
        en1 += __shfl_xor_sync(0xffffffffu, en1, 1);
        en1 += __shfl_xor_sync(0xffffffffu, en1, 2);
        float enA0 = __shfl_sync(0xffffffffu, en0, 8*t);
        float enA1 = __shfl_sync(0xffffffffu, en0, 8*t + 4);
        float enB0 = __shfl_sync(0xffffffffu, en1, 8*t);
        float enB1 = __shfl_sync(0xffffffffu, en1, 8*t + 4);

        // ---- epilogue: dist^2 = qn + en - 2*dot ; out = MARGIN - sqrt(max(.,0)) ----
        #pragma unroll
        for (int mi = 0; mi < 2; mi++) {
            #pragma unroll
            for (int nj = 0; nj < 2; nj++) {
                long long eg = ebase + nbase + nj*8 + cb;
                if (eg < NEI) {   // eg even, NEI even -> pair-safe
                    float el = nj ? enB0 : enA0;
                    float eh = nj ? enB1 : enA1;
                    int row = mi*16 + g;
                    float q0 = qn[row], q1 = qn[row + 8];
                    float d0 = q0 + el - 2.f * c[mi][nj][0];
                    float d1 = q0 + eh - 2.f * c[mi][nj][1];
                    float d2 = q1 + el - 2.f * c[mi][nj][2];
                    float d3 = q1 + eh - 2.f * c[mi][nj][3];
                    float v0 = MARGIN - sqrtf(fmaxf(d0, 0.f));
                    float v1 = MARGIN - sqrtf(fmaxf(d1, 0.f));
                    float v2 = MARGIN - sqrtf(fmaxf(d2, 0.f));
                    float v3 = MARGIN - sqrtf(fmaxf(d3, 0.f));
                    *(float2*)(out + (long long)row * NEI + eg)       = make_float2(v0, v1);
                    *(float2*)(out + (long long)(row + 8) * NEI + eg) = make_float2(v2, v3);
                }
            }
        }
    }
}

extern "C" void kernel_launch(void* const* d_in, const int* in_sizes, int n_in,
                              void* d_out, int out_size) {
    (void)in_sizes; (void)n_in; (void)out_size;
    const void* sub      = d_in[0];
    const void* rel      = d_in[1];
    const float* emb_e   = (const float*)d_in[2];
    const float* emb_rel = (const float*)d_in[3];
    float* out = (float*)d_out;

    int grid = (NEI + EPB - 1) / EPB;   // 391 blocks
    transe_kernel<<<grid, TPB>>>(sub, rel, emb_e, emb_rel, out);
}